// round 4
// baseline (speedup 1.0000x reference)
#include <cuda_runtime.h>
#include <math.h>

#define N_NODES   20000
#define N_EDGES   320000
#define MUL0      64
#define NODE_DIM  240          // 64 + 3*32 + 5*16
#define NUM_BASIS 16
#define NCH       112          // 64 + 32 + 16 fused channels
#define NSTAT     144          // 9 * 16 sufficient statistics per node
#define INV_SQRT_MAXAT 0.0916698497028211f   // 1/sqrt(119)

// Fused projection matrices: M[b][ch] includes one_scalar and 1/sqrt(64)
__device__ float g_M[NUM_BASIS * NCH];
// Per-node sufficient statistics: G[n][j][b] = sum_e sh_e[j] * rbf_e[b]
__device__ float g_stats[(size_t)N_NODES * NSTAT];

// ---------------------------------------------------------------------------
// K1: zero stats array + precompute fused M (merged, wide launch)
// ---------------------------------------------------------------------------
__global__ void setup_kernel(const float* __restrict__ W_rbf,
                             const float* __restrict__ w_expand,
                             const float* __restrict__ b_expand,
                             const float* __restrict__ Wp0,
                             const float* __restrict__ Wp1,
                             const float* __restrict__ Wp2)
{
    int idx = blockIdx.x * blockDim.x + threadIdx.x;
    // zero stats as float4 (NSTAT*4 bytes per node, 16B aligned)
    const int n4 = N_NODES * NSTAT / 4;
    if (idx < n4)
        ((float4*)g_stats)[idx] = make_float4(0.f, 0.f, 0.f, 0.f);

    if (idx >= NUM_BASIS * NCH) return;
    int b  = idx / NCH;
    int ch = idx % NCH;
    float acc = 0.f;
    if (ch < 64) {
        int d = ch;
        #pragma unroll 16
        for (int c = 0; c < 64; ++c)
            acc += W_rbf[b * 192 + c] * (w_expand[c] + b_expand[c]) * Wp0[c * 64 + d];
    } else if (ch < 96) {
        int d = ch - 64;
        #pragma unroll 16
        for (int c = 0; c < 64; ++c)
            acc += W_rbf[b * 192 + 64 + c] * (w_expand[c] + b_expand[c]) * Wp1[c * 32 + d];
    } else {
        int d = ch - 96;
        #pragma unroll 16
        for (int c = 0; c < 64; ++c)
            acc += W_rbf[b * 192 + 128 + c] * (w_expand[c] + b_expand[c]) * Wp2[c * 16 + d];
    }
    g_M[b * NCH + ch] = acc * 0.125f;   // * 1/sqrt(64)
}

// ---------------------------------------------------------------------------
// Vectorized L2 reduction
// ---------------------------------------------------------------------------
__device__ __forceinline__ void red_add_v4(float* addr, float a, float b, float c, float d)
{
    asm volatile("red.global.add.v4.f32 [%0], {%1,%2,%3,%4};"
                 :: "l"(addr), "f"(a), "f"(b), "f"(c), "f"(d) : "memory");
}

// ---------------------------------------------------------------------------
// K2: per-edge rbf + rsh outputs + rank-1 stats accumulation (36 red.v4)
// ---------------------------------------------------------------------------
__global__ void __launch_bounds__(256)
edge_kernel(const float* __restrict__ pos,
            const int*   __restrict__ edge_index,
            float*       __restrict__ rbf_out,
            float*       __restrict__ rsh_out)
{
    int e = blockIdx.x * blockDim.x + threadIdx.x;
    if (e >= N_EDGES) return;

    int src = edge_index[e];
    int dst = edge_index[N_EDGES + e];

    const float* Ps = pos + 3 * src;
    const float* Pd = pos + 3 * dst;
    // reference permutes pos columns to [1,2,0] before differencing
    float vx = Pd[1] - Ps[1];
    float vy = Pd[2] - Ps[2];
    float vz = Pd[0] - Ps[0];

    float d2   = vx * vx + vy * vy + vz * vz;
    float dist = sqrtf(d2);
    float dcl  = fmaxf(dist, 1e-8f);
    float uinv = 1.0f / dcl;
    float x = vx * uinv, y = vy * uinv, z = vz * uinv;

    const float s3  = 1.7320508075688772f;
    const float s5  = 2.23606797749979f;
    const float s15 = 3.872983346207417f;

    float sh[9];
    sh[0] = 1.f;
    sh[1] = s3 * x;
    sh[2] = s3 * y;
    sh[3] = s3 * z;
    sh[4] = s15 * x * z;
    sh[5] = s15 * x * y;
    sh[6] = s5 * (y * y - 0.5f * (x * x + z * z));
    sh[7] = s15 * y * z;
    sh[8] = 0.5f * s15 * (z * z - x * x);

    {
        float* ro = rsh_out + (size_t)e * 9;
        #pragma unroll
        for (int i = 0; i < 9; ++i) ro[i] = sh[i];
    }

    float rbf[16];
    bool active = (dcl < 5.0f);
    if (active) {
        float X  = dcl * 0.2f;
        float X2 = X * X;
        float X5 = X2 * X2 * X;
        float fc = 1.0f + X5 * (-21.0f + X * (35.0f - 15.0f * X));
        float theta = 3.14159265358979323846f * X;
        float s1 = sinf(theta), c1 = cosf(theta);
        float two  = 2.0f * c1;
        float pref = 0.6324555320336759f * uinv * fc;   // sqrt(2/5)/d * fc
        float sp = 0.f, s = s1;
        #pragma unroll
        for (int n = 0; n < 16; ++n) {
            rbf[n] = pref * s;
            float sn = two * s - sp;
            sp = s; s = sn;
        }
    } else {
        #pragma unroll
        for (int n = 0; n < 16; ++n) rbf[n] = 0.f;
    }

    {
        float4* ro = (float4*)(rbf_out + (size_t)e * 16);
        #pragma unroll
        for (int q = 0; q < 4; ++q)
            ro[q] = make_float4(rbf[4 * q], rbf[4 * q + 1], rbf[4 * q + 2], rbf[4 * q + 3]);
    }

    if (!active) return;   // zero contribution

    float* S = g_stats + (size_t)dst * NSTAT;
    #pragma unroll
    for (int j = 0; j < 9; ++j) {
        float sj = sh[j];
        #pragma unroll
        for (int q = 0; q < 4; ++q) {
            red_add_v4(S + j * 16 + 4 * q,
                       sj * rbf[4 * q + 0], sj * rbf[4 * q + 1],
                       sj * rbf[4 * q + 2], sj * rbf[4 * q + 3]);
        }
    }
}

// ---------------------------------------------------------------------------
// K3: warp-per-node projection of 144 stats -> 240 channels (+ node_scalar)
// ---------------------------------------------------------------------------
__global__ void __launch_bounds__(256)
node_kernel(const int*   __restrict__ at_no,
            const float* __restrict__ W_atom,
            const float* __restrict__ b_atom,
            float*       __restrict__ node_emb)
{
    __shared__ float sM[NUM_BASIS * NCH];      // 1792 floats
    __shared__ float sG[8][NSTAT];             // per-warp stats

    for (int i = threadIdx.x; i < NUM_BASIS * NCH; i += blockDim.x)
        sM[i] = g_M[i];
    __syncthreads();

    int warp = threadIdx.x >> 5;
    int lane = threadIdx.x & 31;
    int n = blockIdx.x * 8 + warp;
    if (n >= N_NODES) return;

    // load 144 stats = 36 float4 with 32 lanes: two passes (32 + 4)
    {
        const float4* Sp = (const float4*)(g_stats + (size_t)n * NSTAT);
        ((float4*)sG[warp])[lane] = Sp[lane];
        if (lane < 4) ((float4*)sG[warp])[32 + lane] = Sp[32 + lane];
    }
    __syncwarp();

    const float* G = sG[warp];   // G[j*16 + b]
    int an = at_no[n];
    float* nrow = node_emb + (size_t)n * NODE_DIM;

    #pragma unroll
    for (int q = 0; q < 8; ++q) {
        int ch = lane + 32 * q;
        if (ch < NODE_DIM) {
            float a = 0.f;
            if (ch < 64) {
                #pragma unroll
                for (int b = 0; b < 16; ++b)
                    a = fmaf(G[b], sM[b * NCH + ch], a);
                a += W_atom[an * MUL0 + ch] * INV_SQRT_MAXAT + b_atom[ch];
            } else if (ch < 160) {
                int t = ch - 64;
                int d = t / 3, m = t - 3 * d;          // ch = 64 + 3d + m
                const float* Gp = G + (1 + m) * 16;    // G1[m][.]
                #pragma unroll
                for (int b = 0; b < 16; ++b)
                    a = fmaf(Gp[b], sM[b * NCH + 64 + d], a);
            } else {
                int t = ch - 160;
                int d = t / 5, m = t - 5 * d;          // ch = 160 + 5d + m
                const float* Gp = G + (4 + m) * 16;    // G2[m][.]
                #pragma unroll
                for (int b = 0; b < 16; ++b)
                    a = fmaf(Gp[b], sM[b * NCH + 96 + d], a);
            }
            nrow[ch] = a;
        }
    }
}

// ---------------------------------------------------------------------------
// Launch
// ---------------------------------------------------------------------------
extern "C" void kernel_launch(void* const* d_in, const int* in_sizes, int n_in,
                              void* d_out, int out_size)
{
    const int*   at_no      = (const int*)  d_in[0];
    const float* pos        = (const float*)d_in[1];
    const int*   edge_index = (const int*)  d_in[2];
    const float* W_atom     = (const float*)d_in[3];
    const float* b_atom     = (const float*)d_in[4];
    const float* w_expand   = (const float*)d_in[5];
    const float* b_expand   = (const float*)d_in[6];
    const float* W_rbf      = (const float*)d_in[7];
    const float* Wp0        = (const float*)d_in[8];
    const float* Wp1        = (const float*)d_in[9];
    const float* Wp2        = (const float*)d_in[10];

    float* out      = (float*)d_out;
    float* node_emb = out;                                   // 20000*240
    float* rbf_out  = out + (size_t)N_NODES * NODE_DIM;      // 320000*16
    float* rsh_out  = rbf_out + (size_t)N_EDGES * NUM_BASIS; // 320000*9

    // 1) zero stats + fuse weights
    {
        int total = N_NODES * NSTAT / 4;   // float4 count (dominates 1792)
        setup_kernel<<<(total + 255) / 256, 256>>>(W_rbf, w_expand, b_expand,
                                                   Wp0, Wp1, Wp2);
    }
    // 2) edge kernel: rbf/rsh outputs + rank-1 stats atomics
    edge_kernel<<<(N_EDGES + 255) / 256, 256>>>(pos, edge_index, rbf_out, rsh_out);
    // 3) node kernel: per-node projection + node_scalar
    node_kernel<<<(N_NODES + 7) / 8, 256>>>(at_no, W_atom, b_atom, node_emb);
}

// round 5
// speedup vs baseline: 1.9698x; 1.9698x over previous
#include <cuda_runtime.h>
#include <math.h>

#define N_NODES   20000
#define N_EDGES   320000
#define MUL0      64
#define NODE_DIM  240          // 64 + 3*32 + 5*16
#define NUM_BASIS 16
#define NCH       112          // 64 + 32 + 16 fused channels
#define NSTAT     144          // 9 * 16 sufficient statistics per node
#define INV_SQRT_MAXAT 0.0916698497028211f   // 1/sqrt(119)

// Fused projection matrices: M[b][ch] includes one_scalar and 1/sqrt(64)
__device__ float g_M[NUM_BASIS * NCH];
// Per-node sufficient statistics: G[n][j][b] = sum_e sh_e[j] * rbf_e[b]
__device__ float g_stats[(size_t)N_NODES * NSTAT];

// ---------------------------------------------------------------------------
// K0: zero the stats array (grid-stride float4)
// ---------------------------------------------------------------------------
__global__ void zero_kernel()
{
    const int n4 = N_NODES * NSTAT / 4;
    float4 z = make_float4(0.f, 0.f, 0.f, 0.f);
    for (int i = blockIdx.x * blockDim.x + threadIdx.x; i < n4;
         i += gridDim.x * blockDim.x)
        ((float4*)g_stats)[i] = z;
}

// ---------------------------------------------------------------------------
// K1: precompute fused M — one warp per output element, lanes split c-loop
// ---------------------------------------------------------------------------
__global__ void precompute_M(const float* __restrict__ W_rbf,
                             const float* __restrict__ w_expand,
                             const float* __restrict__ b_expand,
                             const float* __restrict__ Wp0,
                             const float* __restrict__ Wp1,
                             const float* __restrict__ Wp2)
{
    int w    = (blockIdx.x * blockDim.x + threadIdx.x) >> 5;  // output index
    int lane = threadIdx.x & 31;
    if (w >= NUM_BASIS * NCH) return;
    int b  = w / NCH;
    int ch = w % NCH;

    int   roff;
    const float* Wp;
    int   K, d;
    if (ch < 64)       { roff = 0;   Wp = Wp0; K = 64; d = ch; }
    else if (ch < 96)  { roff = 64;  Wp = Wp1; K = 32; d = ch - 64; }
    else               { roff = 128; Wp = Wp2; K = 16; d = ch - 96; }

    float acc = 0.f;
    #pragma unroll
    for (int h = 0; h < 2; ++h) {
        int c = lane + 32 * h;
        acc = fmaf(W_rbf[b * 192 + roff + c] * (w_expand[c] + b_expand[c]),
                   Wp[c * K + d], acc);
    }
    #pragma unroll
    for (int off = 16; off > 0; off >>= 1)
        acc += __shfl_xor_sync(0xffffffffu, acc, off);

    if (lane == 0) g_M[b * NCH + ch] = acc * 0.125f;   // * 1/sqrt(64)
}

// ---------------------------------------------------------------------------
// Vectorized L2 reduction
// ---------------------------------------------------------------------------
__device__ __forceinline__ void red_add_v4(float* addr, float a, float b, float c, float d)
{
    asm volatile("red.global.add.v4.f32 [%0], {%1,%2,%3,%4};"
                 :: "l"(addr), "f"(a), "f"(b), "f"(c), "f"(d) : "memory");
}

// ---------------------------------------------------------------------------
// K2: per-edge rbf + rsh outputs, then warp-cooperative COALESCED stats flush
//     Block = 128 threads (4 warps). Each warp stages its 32 edges' 25 values
//     in shared, then flushes edge-by-edge: lane l -> red.v4 at stats+4l
//     (512 consecutive bytes per instruction instead of 32 scattered lines).
// ---------------------------------------------------------------------------
#define EK_THREADS 128
#define ROWSTRIDE  28          // floats; 112B, 16B-aligned for LDS.128

__global__ void __launch_bounds__(EK_THREADS)
edge_kernel(const float* __restrict__ pos,
            const int*   __restrict__ edge_index,
            float*       __restrict__ rbf_out,
            float*       __restrict__ rsh_out)
{
    __shared__ float sbuf[4][32][ROWSTRIDE];   // [warp][edge][0:16 rbf |16:25 sh]
    __shared__ int   sdst[4][32];

    int tid  = threadIdx.x;
    int warp = tid >> 5;
    int lane = tid & 31;
    int e = blockIdx.x * EK_THREADS + tid;

    bool in_range = (e < N_EDGES);
    bool active = false;
    float* mybuf = sbuf[warp][lane];

    if (in_range) {
        int src = edge_index[e];
        int dst = edge_index[N_EDGES + e];
        sdst[warp][lane] = dst;

        const float* Ps = pos + 3 * src;
        const float* Pd = pos + 3 * dst;
        // reference permutes pos columns to [1,2,0] before differencing
        float vx = Pd[1] - Ps[1];
        float vy = Pd[2] - Ps[2];
        float vz = Pd[0] - Ps[0];

        float d2   = vx * vx + vy * vy + vz * vz;
        float dist = sqrtf(d2);
        float dcl  = fmaxf(dist, 1e-8f);
        float uinv = 1.0f / dcl;
        float x = vx * uinv, y = vy * uinv, z = vz * uinv;

        const float s3  = 1.7320508075688772f;
        const float s5  = 2.23606797749979f;
        const float s15 = 3.872983346207417f;

        float sh[9];
        sh[0] = 1.f;
        sh[1] = s3 * x;
        sh[2] = s3 * y;
        sh[3] = s3 * z;
        sh[4] = s15 * x * z;
        sh[5] = s15 * x * y;
        sh[6] = s5 * (y * y - 0.5f * (x * x + z * z));
        sh[7] = s15 * y * z;
        sh[8] = 0.5f * s15 * (z * z - x * x);

        {
            float* ro = rsh_out + (size_t)e * 9;
            #pragma unroll
            for (int i = 0; i < 9; ++i) ro[i] = sh[i];
        }

        float rbf[16];
        active = (dcl < 5.0f);
        if (active) {
            float X  = dcl * 0.2f;
            float X2 = X * X;
            float X5 = X2 * X2 * X;
            float fc = 1.0f + X5 * (-21.0f + X * (35.0f - 15.0f * X));
            float theta = 3.14159265358979323846f * X;
            float s1 = sinf(theta), c1 = cosf(theta);
            float two  = 2.0f * c1;
            float pref = 0.6324555320336759f * uinv * fc;   // sqrt(2/5)/d * fc
            float sp = 0.f, s = s1;
            #pragma unroll
            for (int n = 0; n < 16; ++n) {
                rbf[n] = pref * s;
                float sn = two * s - sp;
                sp = s; s = sn;
            }
        } else {
            #pragma unroll
            for (int n = 0; n < 16; ++n) rbf[n] = 0.f;
        }

        {
            float4* ro = (float4*)(rbf_out + (size_t)e * 16);
            #pragma unroll
            for (int q = 0; q < 4; ++q)
                ro[q] = make_float4(rbf[4*q], rbf[4*q+1], rbf[4*q+2], rbf[4*q+3]);
        }

        // stage for flush
        #pragma unroll
        for (int i = 0; i < 16; ++i) mybuf[i] = rbf[i];
        #pragma unroll
        for (int j = 0; j < 9; ++j)  mybuf[16 + j] = sh[j];
    }

    unsigned act = __ballot_sync(0xffffffffu, active);
    __syncwarp();

    // warp-cooperative flush: one edge at a time, coalesced red.v4
    while (act) {
        int k = __ffs(act) - 1;
        act &= act - 1;
        const float* eb = sbuf[warp][k];
        float* S = g_stats + (size_t)sdst[warp][k] * NSTAT;

        // lane l -> stats [4l, 4l+4): j = l>>2, rbf base = (l&3)*4
        float  sj = eb[16 + (lane >> 2)];
        float4 r  = *(const float4*)(eb + ((lane & 3) << 2));
        red_add_v4(S + 4 * lane, sj * r.x, sj * r.y, sj * r.z, sj * r.w);

        // stats [128,144): j = 8, lanes 0..3
        if (lane < 4) {
            float  s8 = eb[24];
            float4 r2 = *(const float4*)(eb + (lane << 2));
            red_add_v4(S + 128 + 4 * lane, s8 * r2.x, s8 * r2.y, s8 * r2.z, s8 * r2.w);
        }
    }
}

// ---------------------------------------------------------------------------
// K3: warp-per-node projection of 144 stats -> 240 channels (+ node_scalar)
// ---------------------------------------------------------------------------
__global__ void __launch_bounds__(256)
node_kernel(const int*   __restrict__ at_no,
            const float* __restrict__ W_atom,
            const float* __restrict__ b_atom,
            float*       __restrict__ node_emb)
{
    __shared__ float sM[NUM_BASIS * NCH];      // 1792 floats
    __shared__ float sG[8][NSTAT];             // per-warp stats

    for (int i = threadIdx.x; i < NUM_BASIS * NCH; i += blockDim.x)
        sM[i] = g_M[i];
    __syncthreads();

    int warp = threadIdx.x >> 5;
    int lane = threadIdx.x & 31;
    int n = blockIdx.x * 8 + warp;
    if (n >= N_NODES) return;

    // load 144 stats = 36 float4 with 32 lanes: two passes (32 + 4)
    {
        const float4* Sp = (const float4*)(g_stats + (size_t)n * NSTAT);
        ((float4*)sG[warp])[lane] = Sp[lane];
        if (lane < 4) ((float4*)sG[warp])[32 + lane] = Sp[32 + lane];
    }
    __syncwarp();

    const float* G = sG[warp];   // G[j*16 + b]
    int an = at_no[n];
    float* nrow = node_emb + (size_t)n * NODE_DIM;

    #pragma unroll
    for (int q = 0; q < 8; ++q) {
        int ch = lane + 32 * q;
        if (ch < NODE_DIM) {
            float a = 0.f;
            if (ch < 64) {
                #pragma unroll
                for (int b = 0; b < 16; ++b)
                    a = fmaf(G[b], sM[b * NCH + ch], a);
                a += W_atom[an * MUL0 + ch] * INV_SQRT_MAXAT + b_atom[ch];
            } else if (ch < 160) {
                int t = ch - 64;
                int d = t / 3, m = t - 3 * d;          // ch = 64 + 3d + m
                const float* Gp = G + (1 + m) * 16;    // G1[m][.]
                #pragma unroll
                for (int b = 0; b < 16; ++b)
                    a = fmaf(Gp[b], sM[b * NCH + 64 + d], a);
            } else {
                int t = ch - 160;
                int d = t / 5, m = t - 5 * d;          // ch = 160 + 5d + m
                const float* Gp = G + (4 + m) * 16;    // G2[m][.]
                #pragma unroll
                for (int b = 0; b < 16; ++b)
                    a = fmaf(Gp[b], sM[b * NCH + 96 + d], a);
            }
            nrow[ch] = a;
        }
    }
}

// ---------------------------------------------------------------------------
// Launch
// ---------------------------------------------------------------------------
extern "C" void kernel_launch(void* const* d_in, const int* in_sizes, int n_in,
                              void* d_out, int out_size)
{
    const int*   at_no      = (const int*)  d_in[0];
    const float* pos        = (const float*)d_in[1];
    const int*   edge_index = (const int*)  d_in[2];
    const float* W_atom     = (const float*)d_in[3];
    const float* b_atom     = (const float*)d_in[4];
    const float* w_expand   = (const float*)d_in[5];
    const float* b_expand   = (const float*)d_in[6];
    const float* W_rbf      = (const float*)d_in[7];
    const float* Wp0        = (const float*)d_in[8];
    const float* Wp1        = (const float*)d_in[9];
    const float* Wp2        = (const float*)d_in[10];

    float* out      = (float*)d_out;
    float* node_emb = out;                                   // 20000*240
    float* rbf_out  = out + (size_t)N_NODES * NODE_DIM;      // 320000*16
    float* rsh_out  = rbf_out + (size_t)N_EDGES * NUM_BASIS; // 320000*9

    zero_kernel<<<1184, 256>>>();                             // ~8 blocks/SM
    precompute_M<<<(NUM_BASIS * NCH * 32 + 255) / 256, 256>>>(
        W_rbf, w_expand, b_expand, Wp0, Wp1, Wp2);
    edge_kernel<<<(N_EDGES + EK_THREADS - 1) / EK_THREADS, EK_THREADS>>>(
        pos, edge_index, rbf_out, rsh_out);
    node_kernel<<<(N_NODES + 7) / 8, 256>>>(at_no, W_atom, b_atom, node_emb);
}

// round 7
// speedup vs baseline: 2.3059x; 1.1706x over previous
#include <cuda_runtime.h>
#include <math.h>

#define N_NODES   20000
#define N_EDGES   320000
#define MUL0      64
#define NODE_DIM  240          // 64 + 3*32 + 5*16
#define NUM_BASIS 16
#define NCH       112          // 64 + 32 + 16 fused channels
#define NSTAT     144          // 9 * 16 sufficient statistics per node
#define INV_SQRT_MAXAT 0.0916698497028211f   // 1/sqrt(119)

// Fused projection matrices: M[b][ch] includes one_scalar and 1/sqrt(64)
__device__ float g_M[NUM_BASIS * NCH];
// Per-node sufficient statistics: G[n][j][b] = sum_e sh_e[j] * rbf_e[b]
__device__ float g_stats[(size_t)N_NODES * NSTAT];

// ---------------------------------------------------------------------------
// K0: zero the stats array (grid-stride float4)
// ---------------------------------------------------------------------------
__global__ void zero_kernel()
{
    const int n4 = N_NODES * NSTAT / 4;
    float4 z = make_float4(0.f, 0.f, 0.f, 0.f);
    for (int i = blockIdx.x * blockDim.x + threadIdx.x; i < n4;
         i += gridDim.x * blockDim.x)
        ((float4*)g_stats)[i] = z;
}

// ---------------------------------------------------------------------------
// K1: precompute fused M — one warp per output element, lanes split c-loop
// ---------------------------------------------------------------------------
__global__ void precompute_M(const float* __restrict__ W_rbf,
                             const float* __restrict__ w_expand,
                             const float* __restrict__ b_expand,
                             const float* __restrict__ Wp0,
                             const float* __restrict__ Wp1,
                             const float* __restrict__ Wp2)
{
    int w    = (blockIdx.x * blockDim.x + threadIdx.x) >> 5;  // output index
    int lane = threadIdx.x & 31;
    if (w >= NUM_BASIS * NCH) return;
    int b  = w / NCH;
    int ch = w % NCH;

    int   roff;
    const float* Wp;
    int   K, d;
    if (ch < 64)       { roff = 0;   Wp = Wp0; K = 64; d = ch; }
    else if (ch < 96)  { roff = 64;  Wp = Wp1; K = 32; d = ch - 64; }
    else               { roff = 128; Wp = Wp2; K = 16; d = ch - 96; }

    float acc = 0.f;
    #pragma unroll
    for (int h = 0; h < 2; ++h) {
        int c = lane + 32 * h;
        acc = fmaf(W_rbf[b * 192 + roff + c] * (w_expand[c] + b_expand[c]),
                   Wp[c * K + d], acc);
    }
    #pragma unroll
    for (int off = 16; off > 0; off >>= 1)
        acc += __shfl_xor_sync(0xffffffffu, acc, off);

    if (lane == 0) g_M[b * NCH + ch] = acc * 0.125f;   // * 1/sqrt(64)
}

// ---------------------------------------------------------------------------
// Vectorized L2 reduction
// ---------------------------------------------------------------------------
__device__ __forceinline__ void red_add_v4(float* addr, float a, float b, float c, float d)
{
    asm volatile("red.global.add.v4.f32 [%0], {%1,%2,%3,%4};"
                 :: "l"(addr), "f"(a), "f"(b), "f"(c), "f"(d) : "memory");
}

// ---------------------------------------------------------------------------
// K2: per-edge rbf + rsh outputs, warp-cooperative coalesced stats flush
// ---------------------------------------------------------------------------
#define EK_THREADS 128
#define ROWSTRIDE  28          // floats; 112B, 16B-aligned

__global__ void __launch_bounds__(EK_THREADS)
edge_kernel(const float* __restrict__ pos,
            const int*   __restrict__ edge_index,
            float*       __restrict__ rbf_out,
            float*       __restrict__ rsh_out)
{
    __shared__ float sbuf[4][32][ROWSTRIDE];   // [warp][edge][0:16 rbf |16:25 sh]
    __shared__ int   sdst[4][32];

    int tid  = threadIdx.x;
    int warp = tid >> 5;
    int lane = tid & 31;
    int e = blockIdx.x * EK_THREADS + tid;

    bool in_range = (e < N_EDGES);
    bool active = false;
    float* mybuf = sbuf[warp][lane];

    if (in_range) {
        int src = edge_index[e];
        int dst = edge_index[N_EDGES + e];
        sdst[warp][lane] = dst;

        const float* Ps = pos + 3 * src;
        const float* Pd = pos + 3 * dst;
        // reference permutes pos columns to [1,2,0] before differencing
        float vx = Pd[1] - Ps[1];
        float vy = Pd[2] - Ps[2];
        float vz = Pd[0] - Ps[0];

        float d2   = vx * vx + vy * vy + vz * vz;
        float dist = sqrtf(d2);
        float dcl  = fmaxf(dist, 1e-8f);
        float uinv = 1.0f / dcl;
        float x = vx * uinv, y = vy * uinv, z = vz * uinv;

        const float s3  = 1.7320508075688772f;
        const float s5  = 2.23606797749979f;
        const float s15 = 3.872983346207417f;

        float sh[9];
        sh[0] = 1.f;
        sh[1] = s3 * x;
        sh[2] = s3 * y;
        sh[3] = s3 * z;
        sh[4] = s15 * x * z;
        sh[5] = s15 * x * y;
        sh[6] = s5 * (y * y - 0.5f * (x * x + z * z));
        sh[7] = s15 * y * z;
        sh[8] = 0.5f * s15 * (z * z - x * x);

        {
            float* ro = rsh_out + (size_t)e * 9;
            #pragma unroll
            for (int i = 0; i < 9; ++i) ro[i] = sh[i];
        }

        float rbf[16];
        active = (dcl < 5.0f);
        if (active) {
            float X  = dcl * 0.2f;
            float X2 = X * X;
            float X5 = X2 * X2 * X;
            float fc = 1.0f + X5 * (-21.0f + X * (35.0f - 15.0f * X));
            float theta = 3.14159265358979323846f * X;
            // precise sinf/cosf: MUFU fast path destroys tiny theta
            // (self-loop edges, d ~ 1e-8) via fixed-point argument granularity
            float s1 = sinf(theta), c1 = cosf(theta);
            float two  = 2.0f * c1;
            float pref = 0.6324555320336759f * uinv * fc;   // sqrt(2/5)/d * fc
            float sp = 0.f, s = s1;
            #pragma unroll
            for (int n = 0; n < 16; ++n) {
                rbf[n] = pref * s;
                float sn = two * s - sp;
                sp = s; s = sn;
            }
        } else {
            #pragma unroll
            for (int n = 0; n < 16; ++n) rbf[n] = 0.f;
        }

        {
            float4* ro = (float4*)(rbf_out + (size_t)e * 16);
            #pragma unroll
            for (int q = 0; q < 4; ++q)
                ro[q] = make_float4(rbf[4*q], rbf[4*q+1], rbf[4*q+2], rbf[4*q+3]);
        }

        #pragma unroll
        for (int i = 0; i < 16; ++i) mybuf[i] = rbf[i];
        #pragma unroll
        for (int j = 0; j < 9; ++j)  mybuf[16 + j] = sh[j];
    }

    unsigned act = __ballot_sync(0xffffffffu, active);
    __syncwarp();

    // warp-cooperative flush: one edge at a time, coalesced red.v4
    while (act) {
        int k = __ffs(act) - 1;
        act &= act - 1;
        const float* eb = sbuf[warp][k];
        float* S = g_stats + (size_t)sdst[warp][k] * NSTAT;

        float  sj = eb[16 + (lane >> 2)];
        float4 r  = *(const float4*)(eb + ((lane & 3) << 2));
        red_add_v4(S + 4 * lane, sj * r.x, sj * r.y, sj * r.z, sj * r.w);

        if (lane < 4) {
            float  s8 = eb[24];
            float4 r2 = *(const float4*)(eb + (lane << 2));
            red_add_v4(S + 128 + 4 * lane, s8 * r2.x, s8 * r2.y, s8 * r2.z, s8 * r2.w);
        }
    }
}

// ---------------------------------------------------------------------------
// K3: warp-per-node projection of 144 stats -> 240 channels (+ node_scalar)
//     60 float4-tasks per node; lane handles tasks {lane, lane+32}.
// ---------------------------------------------------------------------------
__device__ __forceinline__ void task_desc(int t, int& goff, int& moff,
                                          int& chbase, int& stride)
{
    if (t < 16) {             // path0: e0 cols 4t..4t+3
        goff = 0; moff = 4 * t; chbase = 4 * t; stride = 1;
    } else if (t < 40) {      // path1: m = p>>3, g = p&7
        int p = t - 16, m = p >> 3, g = p & 7;
        goff = (1 + m) * 16; moff = 64 + 4 * g;
        chbase = 64 + 12 * g + m; stride = 3;
    } else {                  // path2: m = p>>2, g = p&3
        int p = t - 40, m = p >> 2, g = p & 3;
        goff = (4 + m) * 16; moff = 96 + 4 * g;
        chbase = 160 + 20 * g + m; stride = 5;
    }
}

__global__ void __launch_bounds__(256)
node_kernel(const int*   __restrict__ at_no,
            const float* __restrict__ W_atom,
            const float* __restrict__ b_atom,
            float*       __restrict__ node_emb)
{
    __shared__ __align__(16) float sM[NUM_BASIS * NCH];      // 1792 floats
    __shared__ __align__(16) float sG[8][NSTAT];

    for (int i = threadIdx.x; i < NUM_BASIS * NCH; i += blockDim.x)
        sM[i] = g_M[i];
    __syncthreads();

    int warp = threadIdx.x >> 5;
    int lane = threadIdx.x & 31;
    int n = blockIdx.x * 8 + warp;
    if (n >= N_NODES) return;

    // load 144 stats = 36 float4 with 32 lanes (32 + 4)
    {
        const float4* Sp = (const float4*)(g_stats + (size_t)n * NSTAT);
        ((float4*)sG[warp])[lane] = Sp[lane];
        if (lane < 4) ((float4*)sG[warp])[32 + lane] = Sp[32 + lane];
    }
    __syncwarp();

    const float* G = sG[warp];
    int an = at_no[n];
    float* nrow = node_emb + (size_t)n * NODE_DIM;

    // ---- task slot 0: t = lane (always < 60) ----
    {
        int goff, moff, chbase, stride;
        task_desc(lane, goff, moff, chbase, stride);
        float4 acc = make_float4(0.f, 0.f, 0.f, 0.f);
        #pragma unroll
        for (int b = 0; b < 16; ++b) {
            float4 mv = *(const float4*)(sM + b * NCH + moff);
            float  gv = G[goff + b];
            acc.x = fmaf(gv, mv.x, acc.x);
            acc.y = fmaf(gv, mv.y, acc.y);
            acc.z = fmaf(gv, mv.z, acc.z);
            acc.w = fmaf(gv, mv.w, acc.w);
        }
        if (lane < 16) {   // path0: add node_scalar, contiguous float4 store
            float4 wa = *(const float4*)(W_atom + an * MUL0 + chbase);
            float4 ba = *(const float4*)(b_atom + chbase);
            acc.x = fmaf(wa.x, INV_SQRT_MAXAT, ba.x) + acc.x;
            acc.y = fmaf(wa.y, INV_SQRT_MAXAT, ba.y) + acc.y;
            acc.z = fmaf(wa.z, INV_SQRT_MAXAT, ba.z) + acc.z;
            acc.w = fmaf(wa.w, INV_SQRT_MAXAT, ba.w) + acc.w;
            *(float4*)(nrow + chbase) = acc;
        } else {
            nrow[chbase]              = acc.x;
            nrow[chbase + stride]     = acc.y;
            nrow[chbase + 2 * stride] = acc.z;
            nrow[chbase + 3 * stride] = acc.w;
        }
    }

    // ---- task slot 1: t = lane + 32 (valid for lane < 28) ----
    if (lane < 28) {
        int goff, moff, chbase, stride;
        task_desc(lane + 32, goff, moff, chbase, stride);
        float4 acc = make_float4(0.f, 0.f, 0.f, 0.f);
        #pragma unroll
        for (int b = 0; b < 16; ++b) {
            float4 mv = *(const float4*)(sM + b * NCH + moff);
            float  gv = G[goff + b];
            acc.x = fmaf(gv, mv.x, acc.x);
            acc.y = fmaf(gv, mv.y, acc.y);
            acc.z = fmaf(gv, mv.z, acc.z);
            acc.w = fmaf(gv, mv.w, acc.w);
        }
        nrow[chbase]              = acc.x;
        nrow[chbase + stride]     = acc.y;
        nrow[chbase + 2 * stride] = acc.z;
        nrow[chbase + 3 * stride] = acc.w;
    }
}

// ---------------------------------------------------------------------------
// Launch
// ---------------------------------------------------------------------------
extern "C" void kernel_launch(void* const* d_in, const int* in_sizes, int n_in,
                              void* d_out, int out_size)
{
    const int*   at_no      = (const int*)  d_in[0];
    const float* pos        = (const float*)d_in[1];
    const int*   edge_index = (const int*)  d_in[2];
    const float* W_atom     = (const float*)d_in[3];
    const float* b_atom     = (const float*)d_in[4];
    const float* w_expand   = (const float*)d_in[5];
    const float* b_expand   = (const float*)d_in[6];
    const float* W_rbf      = (const float*)d_in[7];
    const float* Wp0        = (const float*)d_in[8];
    const float* Wp1        = (const float*)d_in[9];
    const float* Wp2        = (const float*)d_in[10];

    float* out      = (float*)d_out;
    float* node_emb = out;                                   // 20000*240
    float* rbf_out  = out + (size_t)N_NODES * NODE_DIM;      // 320000*16
    float* rsh_out  = rbf_out + (size_t)N_EDGES * NUM_BASIS; // 320000*9

    zero_kernel<<<1184, 256>>>();
    precompute_M<<<(NUM_BASIS * NCH * 32 + 255) / 256, 256>>>(
        W_rbf, w_expand, b_expand, Wp0, Wp1, Wp2);
    edge_kernel<<<(N_EDGES + EK_THREADS - 1) / EK_THREADS, EK_THREADS>>>(
        pos, edge_index, rbf_out, rsh_out);
    node_kernel<<<(N_NODES + 7) / 8, 256>>>(at_no, W_atom, b_atom, node_emb);
}

// round 8
// speedup vs baseline: 2.5448x; 1.1036x over previous
#include <cuda_runtime.h>
#include <math.h>

#define N_NODES   20000
#define N_EDGES   320000
#define MUL0      64
#define NODE_DIM  240          // 64 + 3*32 + 5*16
#define NUM_BASIS 16
#define NCH       112          // 64 + 32 + 16 fused channels
#define NSTAT     144          // 9 * 16 sufficient statistics per node
#define INV_SQRT_MAXAT 0.0916698497028211f   // 1/sqrt(119)

// Fused projection matrices: M[b][ch] includes one_scalar and 1/sqrt(64)
__device__ float g_M[NUM_BASIS * NCH];
// Per-node sufficient statistics: G[n][j][b] = sum_e sh_e[j] * rbf_e[b]
__device__ float g_stats[(size_t)N_NODES * NSTAT];

// ---------------------------------------------------------------------------
// K1: zero stats (grid-stride) + precompute fused M (warp-per-output), merged
//     Launch exactly 224 blocks x 256 = 1792 warps (one per M element).
// ---------------------------------------------------------------------------
__global__ void __launch_bounds__(256)
setup_kernel(const float* __restrict__ W_rbf,
             const float* __restrict__ w_expand,
             const float* __restrict__ b_expand,
             const float* __restrict__ Wp0,
             const float* __restrict__ Wp1,
             const float* __restrict__ Wp2)
{
    int tid = blockIdx.x * blockDim.x + threadIdx.x;

    // zero stats as float4
    const int n4 = N_NODES * NSTAT / 4;
    float4 z = make_float4(0.f, 0.f, 0.f, 0.f);
    for (int i = tid; i < n4; i += gridDim.x * blockDim.x)
        ((float4*)g_stats)[i] = z;

    // fused M
    int w    = tid >> 5;
    int lane = threadIdx.x & 31;
    if (w >= NUM_BASIS * NCH) return;
    int b  = w / NCH;
    int ch = w % NCH;

    int   roff;
    const float* Wp;
    int   K, d;
    if (ch < 64)       { roff = 0;   Wp = Wp0; K = 64; d = ch; }
    else if (ch < 96)  { roff = 64;  Wp = Wp1; K = 32; d = ch - 64; }
    else               { roff = 128; Wp = Wp2; K = 16; d = ch - 96; }

    float acc = 0.f;
    #pragma unroll
    for (int h = 0; h < 2; ++h) {
        int c = lane + 32 * h;
        acc = fmaf(W_rbf[b * 192 + roff + c] * (w_expand[c] + b_expand[c]),
                   Wp[c * K + d], acc);
    }
    #pragma unroll
    for (int off = 16; off > 0; off >>= 1)
        acc += __shfl_xor_sync(0xffffffffu, acc, off);

    if (lane == 0) g_M[b * NCH + ch] = acc * 0.125f;   // * 1/sqrt(64)
}

// ---------------------------------------------------------------------------
// Vectorized L2 reduction
// ---------------------------------------------------------------------------
__device__ __forceinline__ void red_add_v4(float* addr, float a, float b, float c, float d)
{
    asm volatile("red.global.add.v4.f32 [%0], {%1,%2,%3,%4};"
                 :: "l"(addr), "f"(a), "f"(b), "f"(c), "f"(d) : "memory");
}

// ---------------------------------------------------------------------------
// K2: per-edge rbf + rsh outputs, warp-cooperative coalesced stats flush
// ---------------------------------------------------------------------------
#define EK_THREADS 128
#define ROWSTRIDE  28          // floats; 112B, 16B-aligned

__global__ void __launch_bounds__(EK_THREADS)
edge_kernel(const float* __restrict__ pos,
            const int*   __restrict__ edge_index,
            float*       __restrict__ rbf_out,
            float*       __restrict__ rsh_out)
{
    __shared__ float sbuf[4][32][ROWSTRIDE];   // [warp][edge][0:16 rbf |16:25 sh]
    __shared__ int   sdst[4][32];

    int tid  = threadIdx.x;
    int warp = tid >> 5;
    int lane = tid & 31;
    int e = blockIdx.x * EK_THREADS + tid;

    bool in_range = (e < N_EDGES);
    bool active = false;
    float* mybuf = sbuf[warp][lane];

    if (in_range) {
        int src = edge_index[e];
        int dst = edge_index[N_EDGES + e];
        sdst[warp][lane] = dst;

        const float* Ps = pos + 3 * src;
        const float* Pd = pos + 3 * dst;
        // reference permutes pos columns to [1,2,0] before differencing
        float vx = Pd[1] - Ps[1];
        float vy = Pd[2] - Ps[2];
        float vz = Pd[0] - Ps[0];

        float d2   = vx * vx + vy * vy + vz * vz;
        float dist = sqrtf(d2);
        float dcl  = fmaxf(dist, 1e-8f);
        float uinv = 1.0f / dcl;
        float x = vx * uinv, y = vy * uinv, z = vz * uinv;

        const float s3  = 1.7320508075688772f;
        const float s5  = 2.23606797749979f;
        const float s15 = 3.872983346207417f;

        float sh[9];
        sh[0] = 1.f;
        sh[1] = s3 * x;
        sh[2] = s3 * y;
        sh[3] = s3 * z;
        sh[4] = s15 * x * z;
        sh[5] = s15 * x * y;
        sh[6] = s5 * (y * y - 0.5f * (x * x + z * z));
        sh[7] = s15 * y * z;
        sh[8] = 0.5f * s15 * (z * z - x * x);

        {
            float* ro = rsh_out + (size_t)e * 9;
            #pragma unroll
            for (int i = 0; i < 9; ++i) ro[i] = sh[i];
        }

        float rbf[16];
        active = (dcl < 5.0f);
        if (active) {
            float X  = dcl * 0.2f;
            float X2 = X * X;
            float X5 = X2 * X2 * X;
            float fc = 1.0f + X5 * (-21.0f + X * (35.0f - 15.0f * X));
            float theta = 3.14159265358979323846f * X;
            // precise sinf/cosf: MUFU fast path destroys tiny theta
            // (self-loop edges, d ~ 1e-8) via fixed-point argument granularity
            float s1 = sinf(theta), c1 = cosf(theta);
            float two  = 2.0f * c1;
            float pref = 0.6324555320336759f * uinv * fc;   // sqrt(2/5)/d * fc
            float sp = 0.f, s = s1;
            #pragma unroll
            for (int n = 0; n < 16; ++n) {
                rbf[n] = pref * s;
                float sn = two * s - sp;
                sp = s; s = sn;
            }
        } else {
            #pragma unroll
            for (int n = 0; n < 16; ++n) rbf[n] = 0.f;
        }

        {
            float4* ro = (float4*)(rbf_out + (size_t)e * 16);
            #pragma unroll
            for (int q = 0; q < 4; ++q)
                ro[q] = make_float4(rbf[4*q], rbf[4*q+1], rbf[4*q+2], rbf[4*q+3]);
        }

        #pragma unroll
        for (int i = 0; i < 16; ++i) mybuf[i] = rbf[i];
        #pragma unroll
        for (int j = 0; j < 9; ++j)  mybuf[16 + j] = sh[j];
    }

    unsigned act = __ballot_sync(0xffffffffu, active);
    __syncwarp();

    // warp-cooperative flush: one edge at a time, coalesced red.v4
    while (act) {
        int k = __ffs(act) - 1;
        act &= act - 1;
        const float* eb = sbuf[warp][k];
        float* S = g_stats + (size_t)sdst[warp][k] * NSTAT;

        float  sj = eb[16 + (lane >> 2)];
        float4 r  = *(const float4*)(eb + ((lane & 3) << 2));
        red_add_v4(S + 4 * lane, sj * r.x, sj * r.y, sj * r.z, sj * r.w);

        if (lane < 4) {
            float  s8 = eb[24];
            float4 r2 = *(const float4*)(eb + (lane << 2));
            red_add_v4(S + 128 + 4 * lane, s8 * r2.x, s8 * r2.y, s8 * r2.z, s8 * r2.w);
        }
    }
}

// ---------------------------------------------------------------------------
// K3: node projection with M in REGISTERS.
//     128 threads/block = 120 half-tasks (2 output columns each).
//     Each thread preloads its 32 M values once, then loops over 32 nodes
//     (4 per sync round; G rows staged in smem; G reads are warp-broadcast).
// ---------------------------------------------------------------------------
#define NB              4      // nodes per sync round
#define NODES_PER_BLOCK 32

__device__ __forceinline__ void task_desc(int t, int& goff, int& moff,
                                          int& chbase, int& stride)
{
    if (t < 16) {             // path0: e0 cols 4t..4t+3
        goff = 0; moff = 4 * t; chbase = 4 * t; stride = 1;
    } else if (t < 40) {      // path1: m = p>>3, g = p&7
        int p = t - 16, m = p >> 3, g = p & 7;
        goff = (1 + m) * 16; moff = 64 + 4 * g;
        chbase = 64 + 12 * g + m; stride = 3;
    } else {                  // path2: m = p>>2, g = p&3
        int p = t - 40, m = p >> 2, g = p & 3;
        goff = (4 + m) * 16; moff = 96 + 4 * g;
        chbase = 160 + 20 * g + m; stride = 5;
    }
}

__global__ void __launch_bounds__(128)
node_kernel(const int*   __restrict__ at_no,
            const float* __restrict__ W_atom,
            const float* __restrict__ b_atom,
            float*       __restrict__ node_emb)
{
    __shared__ __align__(16) float sG[NB * NSTAT];   // 4 nodes x 144

    int t = threadIdx.x;
    bool tvalid = (t < 120);

    int task = t >> 1, half = t & 1;
    int goff = 0, moff = 0, chbase = 0, stride = 1;
    if (tvalid) task_desc(task, goff, moff, chbase, stride);
    int col0 = moff + 2 * half;                        // M columns col0, col0+1
    int ch0  = chbase + (2 * half) * stride;
    int ch1  = chbase + (2 * half + 1) * stride;

    // preload M columns into registers
    float m0[16], m1[16];
    if (tvalid) {
        #pragma unroll
        for (int b = 0; b < 16; ++b) {
            m0[b] = g_M[b * NCH + col0];
            m1[b] = g_M[b * NCH + col0 + 1];
        }
    }

    int nbase0 = blockIdx.x * NODES_PER_BLOCK;

    for (int it = 0; it < NODES_PER_BLOCK / NB; ++it) {
        int nbase = nbase0 + it * NB;

        __syncthreads();   // previous round's sG fully consumed
        {
            const float4* Sp = (const float4*)(g_stats + (size_t)nbase * NSTAT);
            float4* Dp = (float4*)sG;
            Dp[t] = Sp[t];                                     // 0..127
            if (t < NB * (NSTAT / 4) - 128) Dp[128 + t] = Sp[128 + t];  // 128..143
        }
        __syncthreads();

        if (tvalid) {
            #pragma unroll
            for (int k = 0; k < NB; ++k) {
                int n = nbase + k;
                const float* G = sG + k * NSTAT;
                float a0 = 0.f, a1 = 0.f;
                #pragma unroll
                for (int b = 0; b < 16; ++b) {
                    float g = G[goff + b];
                    a0 = fmaf(g, m0[b], a0);
                    a1 = fmaf(g, m1[b], a1);
                }
                float* nrow = node_emb + (size_t)n * NODE_DIM;
                if (t < 32) {
                    // path0: ch0 = 2t, ch1 = 2t+1 consecutive -> float2
                    int an = at_no[n];
                    float2 wa = *(const float2*)(W_atom + an * MUL0 + ch0);
                    float2 ba = *(const float2*)(b_atom + ch0);
                    a0 += fmaf(wa.x, INV_SQRT_MAXAT, ba.x);
                    a1 += fmaf(wa.y, INV_SQRT_MAXAT, ba.y);
                    *(float2*)(nrow + ch0) = make_float2(a0, a1);
                } else {
                    nrow[ch0] = a0;
                    nrow[ch1] = a1;
                }
            }
        }
    }
}

// ---------------------------------------------------------------------------
// Launch
// ---------------------------------------------------------------------------
extern "C" void kernel_launch(void* const* d_in, const int* in_sizes, int n_in,
                              void* d_out, int out_size)
{
    const int*   at_no      = (const int*)  d_in[0];
    const float* pos        = (const float*)d_in[1];
    const int*   edge_index = (const int*)  d_in[2];
    const float* W_atom     = (const float*)d_in[3];
    const float* b_atom     = (const float*)d_in[4];
    const float* w_expand   = (const float*)d_in[5];
    const float* b_expand   = (const float*)d_in[6];
    const float* W_rbf      = (const float*)d_in[7];
    const float* Wp0        = (const float*)d_in[8];
    const float* Wp1        = (const float*)d_in[9];
    const float* Wp2        = (const float*)d_in[10];

    float* out      = (float*)d_out;
    float* node_emb = out;                                   // 20000*240
    float* rbf_out  = out + (size_t)N_NODES * NODE_DIM;      // 320000*16
    float* rsh_out  = rbf_out + (size_t)N_EDGES * NUM_BASIS; // 320000*9

    setup_kernel<<<224, 256>>>(W_rbf, w_expand, b_expand, Wp0, Wp1, Wp2);
    edge_kernel<<<(N_EDGES + EK_THREADS - 1) / EK_THREADS, EK_THREADS>>>(
        pos, edge_index, rbf_out, rsh_out);
    node_kernel<<<N_NODES / NODES_PER_BLOCK, 128>>>(at_no, W_atom, b_atom, node_emb);
}